// round 1
// baseline (speedup 1.0000x reference)
#include <cuda_runtime.h>
#include <cuda_bf16.h>
#include <math.h>

// ---------------------------------------------------------------------------
// Problem constants
// ---------------------------------------------------------------------------
#define S_ 32
#define B_ 2048
#define M_ 16
#define N_ 8
#define H_ 240          // gru hidden
#define IN_ 48          // dnn input
#define O1_ 512         // fc1 out
#define MN_ 128         // M*N
#define ROWS_ (S_ * B_) // 65536

// ---------------------------------------------------------------------------
// Scratch (device globals; allocation-free by construction)
// ---------------------------------------------------------------------------
__device__ float g_x1[ROWS_ * H_];        // 63 MB
__device__ float g_gi[ROWS_ * 3 * H_];    // 189 MB
__device__ float g_gh[ROWS_ * 3 * H_];    // 189 MB
__device__ float g_hdrop[ROWS_ * H_];     // 63 MB
__device__ float g_x2d[ROWS_ * O1_];      // 134 MB
__device__ float g_feat[B_ * IN_];
__device__ float g_innov[B_ * N_];
__device__ double g_reg[3];

// ---------------------------------------------------------------------------
// Concrete-dropout factor: x * (1 - z) / (1 - p), z = sigmoid((plog+logit(u))/T)
// ---------------------------------------------------------------------------
__device__ __forceinline__ float cfac(float u, float plog, float inv1mp) {
    float t = plog + __logf(u) - log1pf(-u);
    float z = 1.0f / (1.0f + __expf(-10.0f * t));   // TEMP = 0.1
    return (1.0f - z) * inv1mp;
}
__device__ __forceinline__ float sigm(float x) {
    return 1.0f / (1.0f + __expf(-x));
}

// ---------------------------------------------------------------------------
// Prep: xbar (ensemble mean), x_pred_mean, innovation, 48-dim feature per b
// One block handles 16 b's. grid = B/16 = 128, 256 threads.
// ---------------------------------------------------------------------------
__global__ void k_prep(const float* __restrict__ y_t,
                       const float* __restrict__ x_ens,
                       const float* __restrict__ x_prev_prev_mean,
                       const float* __restrict__ x_pred_prev_mean,
                       const float* __restrict__ y_prev,
                       const float* __restrict__ F,
                       const float* __restrict__ Hm,
                       float* __restrict__ feat,
                       float* __restrict__ innov) {
    __shared__ float sF[M_ * M_];
    __shared__ float sH[N_ * M_];
    __shared__ float sxbar[16][M_];
    __shared__ float sxpm[16][M_];
    __shared__ float sinn[16][N_];
    int tid = threadIdx.x;
    if (tid < M_ * M_) sF[tid] = F[tid];
    if (tid < N_ * M_) sH[tid] = Hm[tid];
    int bl = tid >> 4;          // 0..15
    int m  = tid & 15;          // 0..15
    int b = blockIdx.x * 16 + bl;

    float s = 0.0f;
    #pragma unroll 4
    for (int si = 0; si < S_; si++)
        s += x_ens[((size_t)si * B_ + b) * M_ + m];
    sxbar[bl][m] = s * (1.0f / S_);
    __syncthreads();

    // x_pred_mean[k] = sum_j F[k][j] * xbar[j]
    float xp = 0.0f;
    #pragma unroll
    for (int j = 0; j < M_; j++) xp += sF[m * M_ + j] * sxbar[bl][j];
    sxpm[bl][m] = xp;
    __syncthreads();

    if (m < N_) {
        float yp = 0.0f;
        #pragma unroll
        for (int j = 0; j < M_; j++) yp += sH[m * M_ + j] * sxpm[bl][j];
        float inn = y_t[b * N_ + m] - yp;
        sinn[bl][m] = inn;
        innov[b * N_ + m] = inn;
    }
    __syncthreads();

    for (int e = tid; e < 16 * IN_; e += 256) {
        int bb = e / IN_, c = e % IN_;
        int gb = blockIdx.x * 16 + bb;
        float v;
        if (c < 16)       v = sxbar[bb][c]      - x_pred_prev_mean[gb * M_ + c];
        else if (c < 24)  v = sinn[bb][c - 16];
        else if (c < 40)  v = sxbar[bb][c - 24] - x_prev_prev_mean[gb * M_ + (c - 24)];
        else              v = y_t[gb * N_ + (c - 40)] - y_prev[gb * N_ + (c - 40)];
        feat[gb * IN_ + c] = v;
    }
}

// ---------------------------------------------------------------------------
// Generic tiled SGEMM: out[row, n] = act( sum_k A[row,k]*W[n,k] + bias[n] )
//   BM=128, BN=64, BK=16, 256 threads, 8x4 per-thread tile.
//   DROP_IN : A element = feat[(row & (B-1))*K + k] * cfac(u_in[row*K+k])
//   DROP_OUT: output *= cfac(u_out[row*Nout+n])
// Mrows assumed multiple of 128; K multiple of 16; Nout multiple of 16.
// ---------------------------------------------------------------------------
template <bool DROP_IN, bool RELU, bool DROP_OUT>
__global__ __launch_bounds__(256) void gemm_kernel(
    const float* __restrict__ A, const float* __restrict__ W,
    const float* __restrict__ bias, float* __restrict__ out,
    int Nout, int K,
    const float* __restrict__ featp, const float* __restrict__ u_in,
    const float* __restrict__ p_in_ptr,
    const float* __restrict__ u_out, const float* __restrict__ p_out_ptr) {
    const int BM = 128, BN = 64, BK = 16;
    __shared__ float As[BK][BM + 4];
    __shared__ float Bs[BK][BN + 4];
    int tid = threadIdx.x;
    int row0 = blockIdx.x * BM;
    int n0   = blockIdx.y * BN;

    float pin = 0.0f, inv1mp_in = 0.0f, pout = 0.0f, inv1mp_out = 0.0f;
    if (DROP_IN)  { pin  = *p_in_ptr;  inv1mp_in  = 1.0f + __expf(pin);  }
    if (DROP_OUT) { pout = *p_out_ptr; inv1mp_out = 1.0f + __expf(pout); }

    int a_m = tid >> 2;            // 0..63
    int a_k = (tid & 3) * 4;       // {0,4,8,12}
    int tx = tid & 15;             // n = tx*4
    int ty = tid >> 4;             // rows ty*8 .. +7

    float acc[8][4];
    #pragma unroll
    for (int i = 0; i < 8; i++)
        #pragma unroll
        for (int j = 0; j < 4; j++) acc[i][j] = 0.0f;

    for (int k0 = 0; k0 < K; k0 += BK) {
        // --- load A tile (128 x 16), two passes of 64 rows ---
        #pragma unroll
        for (int p = 0; p < 2; p++) {
            int mloc = a_m + p * 64;
            int row = row0 + mloc;
            float4 v;
            if (!DROP_IN) {
                v = *(const float4*)(A + (size_t)row * K + k0 + a_k);
            } else {
                int b = row & (B_ - 1);
                float4 f = *(const float4*)(featp + (size_t)b * K + k0 + a_k);
                float4 uu = *(const float4*)(u_in + (size_t)row * K + k0 + a_k);
                v.x = f.x * cfac(uu.x, pin, inv1mp_in);
                v.y = f.y * cfac(uu.y, pin, inv1mp_in);
                v.z = f.z * cfac(uu.z, pin, inv1mp_in);
                v.w = f.w * cfac(uu.w, pin, inv1mp_in);
            }
            As[a_k + 0][mloc] = v.x; As[a_k + 1][mloc] = v.y;
            As[a_k + 2][mloc] = v.z; As[a_k + 3][mloc] = v.w;
        }
        // --- load B tile (64 x 16) with Nout guard ---
        {
            int nloc = a_m;
            float4 v = make_float4(0.f, 0.f, 0.f, 0.f);
            if (n0 + nloc < Nout)
                v = *(const float4*)(W + (size_t)(n0 + nloc) * K + k0 + a_k);
            Bs[a_k + 0][nloc] = v.x; Bs[a_k + 1][nloc] = v.y;
            Bs[a_k + 2][nloc] = v.z; Bs[a_k + 3][nloc] = v.w;
        }
        __syncthreads();
        #pragma unroll
        for (int k = 0; k < BK; k++) {
            float a[8], bb[4];
            float4 t0 = *(const float4*)&As[k][ty * 8];
            float4 t1 = *(const float4*)&As[k][ty * 8 + 4];
            a[0] = t0.x; a[1] = t0.y; a[2] = t0.z; a[3] = t0.w;
            a[4] = t1.x; a[5] = t1.y; a[6] = t1.z; a[7] = t1.w;
            float4 u4 = *(const float4*)&Bs[k][tx * 4];
            bb[0] = u4.x; bb[1] = u4.y; bb[2] = u4.z; bb[3] = u4.w;
            #pragma unroll
            for (int i = 0; i < 8; i++)
                #pragma unroll
                for (int j = 0; j < 4; j++)
                    acc[i][j] = fmaf(a[i], bb[j], acc[i][j]);
        }
        __syncthreads();
    }

    int n = n0 + tx * 4;
    if (n < Nout) {
        float b0 = bias[n + 0], b1 = bias[n + 1], b2 = bias[n + 2], b3 = bias[n + 3];
        #pragma unroll
        for (int i = 0; i < 8; i++) {
            int row = row0 + ty * 8 + i;
            float4 r;
            r.x = acc[i][0] + b0; r.y = acc[i][1] + b1;
            r.z = acc[i][2] + b2; r.w = acc[i][3] + b3;
            if (RELU) {
                r.x = fmaxf(r.x, 0.f); r.y = fmaxf(r.y, 0.f);
                r.z = fmaxf(r.z, 0.f); r.w = fmaxf(r.w, 0.f);
            }
            if (DROP_OUT) {
                const float* up = u_out + (size_t)row * Nout + n;
                r.x *= cfac(up[0], pout, inv1mp_out);
                r.y *= cfac(up[1], pout, inv1mp_out);
                r.z *= cfac(up[2], pout, inv1mp_out);
                r.w *= cfac(up[3], pout, inv1mp_out);
            }
            *(float4*)(out + (size_t)row * Nout + n) = r;
        }
    }
}

// ---------------------------------------------------------------------------
// GRU gate fusion + dropout on h_new. grid = ROWS blocks, 256 threads.
// ---------------------------------------------------------------------------
__global__ void k_gru(const float* __restrict__ gi, const float* __restrict__ gh,
                      const float* __restrict__ h_ens,
                      const float* __restrict__ u_fc1,
                      const float* __restrict__ p_fc1_ptr,
                      float* __restrict__ hdrop) {
    int row = blockIdx.x;
    int j = threadIdx.x;
    if (j >= H_) return;
    size_t gbase = (size_t)row * (3 * H_);
    float ir = gi[gbase + j], iz = gi[gbase + H_ + j], in_ = gi[gbase + 2 * H_ + j];
    float hr = gh[gbase + j], hz = gh[gbase + H_ + j], hn = gh[gbase + 2 * H_ + j];
    float r = sigm(ir + hr);
    float z = sigm(iz + hz);
    float ng = tanhf(in_ + r * hn);
    float h  = h_ens[(size_t)row * H_ + j];
    float hnew = (1.0f - z) * ng + z * h;
    float plog = *p_fc1_ptr;
    float inv1mp = 1.0f + __expf(plog);
    hdrop[(size_t)row * H_ + j] = hnew * cfac(u_fc1[(size_t)row * H_ + j], plog, inv1mp);
}

// ---------------------------------------------------------------------------
// fc2 GEMM (K=512, Nout=128) with fused Kalman epilogue:
//   x_filt[row,m] = (F @ x_ens[row])[m] + sum_n Kv[m*8+n]*innov[b,n]
// BM=64 rows/block, full 128 outputs. grid = ROWS/64 = 1024, 256 threads.
// ---------------------------------------------------------------------------
__global__ __launch_bounds__(256) void k_fc2_epi(
    const float* __restrict__ A,        // x2d [ROWS,512]
    const float* __restrict__ W,        // W_fc2 [128,512]
    const float* __restrict__ bias,     // b_fc2 [128]
    const float* __restrict__ x_ens,    // [S,B,M]
    const float* __restrict__ F,        // [16,16]
    const float* __restrict__ innov,    // [B,8]
    float* __restrict__ out) {          // x_filt [S,B,M]
    const int BM = 64, BN = 128, BK = 16, K = O1_;
    __shared__ float As[BK][BM + 4];
    __shared__ float Bs[BK][BN + 4];
    __shared__ float sKv[BM][BN];
    __shared__ float sF[M_ * M_];
    __shared__ float sinn[BM][N_];
    int tid = threadIdx.x;
    int row0 = blockIdx.x * BM;
    if (tid < M_ * M_) sF[tid] = F[tid];
    {
        int b0 = row0 & (B_ - 1);
        for (int e = tid; e < BM * N_; e += 256)
            sinn[e >> 3][e & 7] = innov[(b0 + (e >> 3)) * N_ + (e & 7)];
    }
    int a_m = tid >> 2;
    int a_k = (tid & 3) * 4;
    int tx = tid & 31;   // n = tx*4
    int ty = tid >> 5;   // rows ty*8 .. +7

    float acc[8][4];
    #pragma unroll
    for (int i = 0; i < 8; i++)
        #pragma unroll
        for (int j = 0; j < 4; j++) acc[i][j] = 0.0f;

    for (int k0 = 0; k0 < K; k0 += BK) {
        {   // A tile 64x16: one float4/thread
            float4 v = *(const float4*)(A + (size_t)(row0 + a_m) * K + k0 + a_k);
            As[a_k + 0][a_m] = v.x; As[a_k + 1][a_m] = v.y;
            As[a_k + 2][a_m] = v.z; As[a_k + 3][a_m] = v.w;
        }
        #pragma unroll
        for (int p = 0; p < 2; p++) {   // B tile 128x16
            int nloc = a_m + p * 64;
            float4 v = *(const float4*)(W + (size_t)nloc * K + k0 + a_k);
            Bs[a_k + 0][nloc] = v.x; Bs[a_k + 1][nloc] = v.y;
            Bs[a_k + 2][nloc] = v.z; Bs[a_k + 3][nloc] = v.w;
        }
        __syncthreads();
        #pragma unroll
        for (int k = 0; k < BK; k++) {
            float a[8], bb[4];
            float4 t0 = *(const float4*)&As[k][ty * 8];
            float4 t1 = *(const float4*)&As[k][ty * 8 + 4];
            a[0] = t0.x; a[1] = t0.y; a[2] = t0.z; a[3] = t0.w;
            a[4] = t1.x; a[5] = t1.y; a[6] = t1.z; a[7] = t1.w;
            float4 u4 = *(const float4*)&Bs[k][tx * 4];
            bb[0] = u4.x; bb[1] = u4.y; bb[2] = u4.z; bb[3] = u4.w;
            #pragma unroll
            for (int i = 0; i < 8; i++)
                #pragma unroll
                for (int j = 0; j < 4; j++)
                    acc[i][j] = fmaf(a[i], bb[j], acc[i][j]);
        }
        __syncthreads();
    }
    {   // stage Kv (+bias) to smem
        int n = tx * 4;
        float b0 = bias[n + 0], b1 = bias[n + 1], b2 = bias[n + 2], b3 = bias[n + 3];
        #pragma unroll
        for (int i = 0; i < 8; i++) {
            float4 r;
            r.x = acc[i][0] + b0; r.y = acc[i][1] + b1;
            r.z = acc[i][2] + b2; r.w = acc[i][3] + b3;
            *(float4*)&sKv[ty * 8 + i][n] = r;
        }
    }
    __syncthreads();
    // epilogue: 64 rows x 16 m = 1024 outputs
    for (int e = tid; e < BM * M_; e += 256) {
        int i = e >> 4, m = e & 15;
        int row = row0 + i;
        const float* xr = x_ens + (size_t)row * M_;
        float xp = 0.0f;
        #pragma unroll
        for (int j = 0; j < M_; j++) xp += sF[m * M_ + j] * xr[j];
        float corr = 0.0f;
        #pragma unroll
        for (int n = 0; n < N_; n++) corr += sKv[i][m * N_ + n] * sinn[i][n];
        out[(size_t)row * M_ + m] = xp + corr;
    }
}

// ---------------------------------------------------------------------------
// Regularizer: per-layer sum(W^2) in double (3 blocks, deterministic), then
// finalize writes raw_reg[S] at d_out + S*B*M.
// ---------------------------------------------------------------------------
__global__ void k_reg_sums(const float* __restrict__ W_in,
                           const float* __restrict__ W_fc1,
                           const float* __restrict__ W_fc2,
                           double* __restrict__ reg) {
    __shared__ double sd[256];
    int l = blockIdx.x;
    const float* W = (l == 0) ? W_in : (l == 1) ? W_fc1 : W_fc2;
    int n = (l == 0) ? H_ * IN_ : (l == 1) ? O1_ * H_ : MN_ * O1_;
    double s = 0.0;
    for (int i = threadIdx.x; i < n; i += blockDim.x) {
        float w = W[i];
        s += (double)w * (double)w;
    }
    sd[threadIdx.x] = s;
    __syncthreads();
    for (int o = 128; o > 0; o >>= 1) {
        if (threadIdx.x < o) sd[threadIdx.x] += sd[threadIdx.x + o];
        __syncthreads();
    }
    if (threadIdx.x == 0) reg[l] = sd[0];
}

__global__ void k_reg_final(const double* __restrict__ reg,
                            const float* __restrict__ p_in,
                            const float* __restrict__ p_fc1,
                            const float* __restrict__ p_fc2,
                            float* __restrict__ out_reg) {
    double tot = 0.0;
    float pl[3] = {*p_in, *p_fc1, *p_fc2};
    double fan[3] = {(double)IN_, (double)H_, (double)O1_};
    #pragma unroll
    for (int l = 0; l < 3; l++) {
        double p = 1.0 / (1.0 + exp(-(double)pl[l]));
        tot += reg[l] / (1.0 - p) + fan[l] * (p * log(p) + (1.0 - p) * log1p(-p));
    }
    int s = threadIdx.x;
    if (s < S_) out_reg[s] = (float)tot;
}

// ---------------------------------------------------------------------------
// Launch
// ---------------------------------------------------------------------------
extern "C" void kernel_launch(void* const* d_in, const int* in_sizes, int n_in,
                              void* d_out, int out_size) {
    const float* y_t    = (const float*)d_in[0];
    const float* x_ens  = (const float*)d_in[1];
    const float* xppm   = (const float*)d_in[2];   // x_prev_prev_mean
    const float* xpdm   = (const float*)d_in[3];   // x_pred_prev_mean
    const float* y_prev = (const float*)d_in[4];
    const float* h_ens  = (const float*)d_in[5];
    const float* F      = (const float*)d_in[6];
    const float* Hm     = (const float*)d_in[7];
    const float* W_in   = (const float*)d_in[8];
    const float* b_in   = (const float*)d_in[9];
    const float* W_ih   = (const float*)d_in[10];
    const float* b_ih   = (const float*)d_in[11];
    const float* W_hh   = (const float*)d_in[12];
    const float* b_hh   = (const float*)d_in[13];
    const float* W_fc1  = (const float*)d_in[14];
    const float* b_fc1  = (const float*)d_in[15];
    const float* W_fc2  = (const float*)d_in[16];
    const float* b_fc2  = (const float*)d_in[17];
    const float* p_in   = (const float*)d_in[18];
    const float* p_fc1  = (const float*)d_in[19];
    const float* p_fc2  = (const float*)d_in[20];
    const float* u_in   = (const float*)d_in[21];
    const float* u_fc1  = (const float*)d_in[22];
    const float* u_fc2  = (const float*)d_in[23];

    float *x1p, *gip, *ghp, *hdp, *x2p, *featp, *innp;
    double* regp;
    cudaGetSymbolAddress((void**)&x1p, g_x1);
    cudaGetSymbolAddress((void**)&gip, g_gi);
    cudaGetSymbolAddress((void**)&ghp, g_gh);
    cudaGetSymbolAddress((void**)&hdp, g_hdrop);
    cudaGetSymbolAddress((void**)&x2p, g_x2d);
    cudaGetSymbolAddress((void**)&featp, g_feat);
    cudaGetSymbolAddress((void**)&innp, g_innov);
    cudaGetSymbolAddress((void**)&regp, g_reg);

    float* out = (float*)d_out;

    k_prep<<<B_ / 16, 256>>>(y_t, x_ens, xppm, xpdm, y_prev, F, Hm, featp, innp);
    k_reg_sums<<<3, 256>>>(W_in, W_fc1, W_fc2, regp);

    // x1 = relu(cdrop(feat, u_in) @ W_in^T + b_in)
    gemm_kernel<true, true, false><<<dim3(ROWS_ / 128, (H_ + 63) / 64), 256>>>(
        nullptr, W_in, b_in, x1p, H_, IN_, featp, u_in, p_in, nullptr, nullptr);

    // gi = x1 @ W_ih^T + b_ih ; gh = h_ens @ W_hh^T + b_hh
    gemm_kernel<false, false, false><<<dim3(ROWS_ / 128, (3 * H_ + 63) / 64), 256>>>(
        x1p, W_ih, b_ih, gip, 3 * H_, H_, nullptr, nullptr, nullptr, nullptr, nullptr);
    gemm_kernel<false, false, false><<<dim3(ROWS_ / 128, (3 * H_ + 63) / 64), 256>>>(
        h_ens, W_hh, b_hh, ghp, 3 * H_, H_, nullptr, nullptr, nullptr, nullptr, nullptr);

    // GRU gates -> hdrop = cdrop(h_new, u_fc1)
    k_gru<<<ROWS_, 256>>>(gip, ghp, h_ens, u_fc1, p_fc1, hdp);

    // x2d = cdrop(relu(hdrop @ W_fc1^T + b_fc1), u_fc2)
    gemm_kernel<false, true, true><<<dim3(ROWS_ / 128, O1_ / 64), 256>>>(
        hdp, W_fc1, b_fc1, x2p, O1_, H_, nullptr, nullptr, nullptr, u_fc2, p_fc2);

    // Kv = x2d @ W_fc2^T + b_fc2 ; x_filt = F@x_ens + K@innov  (fused)
    k_fc2_epi<<<ROWS_ / 64, 256>>>(x2p, W_fc2, b_fc2, x_ens, F, innp, out);

    // raw_reg
    k_reg_final<<<1, 32>>>(regp, p_in, p_fc1, p_fc2, out + (size_t)ROWS_ * M_);
}

// round 4
// speedup vs baseline: 1.6295x; 1.6295x over previous
#include <cuda_runtime.h>
#include <cuda_bf16.h>
#include <math.h>
#include <stdint.h>

#define S_ 32
#define B_ 2048
#define M_ 16
#define N_ 8
#define H_ 240
#define IN_ 48
#define O1_ 512
#define ROWS_ (S_ * B_)

// ---------------- scratch ----------------
__device__ __align__(16) __nv_bfloat16 g_fh[ROWS_ * 64], g_fl[ROWS_ * 64];
__device__ __align__(16) __nv_bfloat16 g_x1h[(size_t)ROWS_ * 256], g_x1l[(size_t)ROWS_ * 256];
__device__ __align__(16) __nv_bfloat16 g_hh[(size_t)ROWS_ * 256], g_hl[(size_t)ROWS_ * 256];
__device__ __align__(16) __nv_bfloat16 g_hdh[(size_t)ROWS_ * 256], g_hdl[(size_t)ROWS_ * 256];
__device__ __align__(16) __nv_bfloat16 g_x2h[(size_t)ROWS_ * 512], g_x2l[(size_t)ROWS_ * 512];
__device__ float g_gi[(size_t)ROWS_ * 720];
__device__ float g_gh[(size_t)ROWS_ * 720];
__device__ float g_kv[(size_t)ROWS_ * 128];
__device__ __align__(16) float g_feat[B_ * IN_];
__device__ float g_innov[B_ * N_];
__device__ double g_reg[3];
// padded bf16 weight planes [NoutPad][Kpad]
__device__ __align__(16) __nv_bfloat16 g_wi_h[256 * 64],  g_wi_l[256 * 64];
__device__ __align__(16) __nv_bfloat16 g_wih_h[768 * 256], g_wih_l[768 * 256];
__device__ __align__(16) __nv_bfloat16 g_whh_h[768 * 256], g_whh_l[768 * 256];
__device__ __align__(16) __nv_bfloat16 g_wf1_h[512 * 256], g_wf1_l[512 * 256];
__device__ __align__(16) __nv_bfloat16 g_wf2_h[128 * 512], g_wf2_l[128 * 512];

// ---------------- helpers ----------------
__device__ __forceinline__ float cfac(float u, float plog, float inv1mp) {
    float t = plog + __logf(u) - log1pf(-u);
    float z = 1.0f / (1.0f + __expf(-10.0f * t));
    return (1.0f - z) * inv1mp;
}
__device__ __forceinline__ float sigm(float x) { return 1.0f / (1.0f + __expf(-x)); }
__device__ __forceinline__ void split_bf16(float v, __nv_bfloat16& h, __nv_bfloat16& l) {
    h = __float2bfloat16_rn(v);
    l = __float2bfloat16_rn(v - __bfloat162float(h));
}
__device__ __forceinline__ uint32_t smem_u32(const void* p) {
    uint32_t a;
    asm("{ .reg .u64 t; cvta.to.shared.u64 t, %1; cvt.u32.u64 %0, t; }" : "=r"(a) : "l"(p));
    return a;
}
__device__ __forceinline__ void cp16(uint32_t dst, const void* src) {
    asm volatile("cp.async.cg.shared.global [%0], [%1], 16;" :: "r"(dst), "l"(src));
}
#define CP_COMMIT() asm volatile("cp.async.commit_group;" ::: "memory")
__device__ __forceinline__ void ldm4(uint32_t* r, uint32_t addr) {
    asm volatile("ldmatrix.sync.aligned.m8n8.x4.shared.b16 {%0,%1,%2,%3}, [%4];"
                 : "=r"(r[0]), "=r"(r[1]), "=r"(r[2]), "=r"(r[3]) : "r"(addr));
}
__device__ __forceinline__ void mma16816(float* d, const uint32_t* a, const uint32_t* b) {
    asm volatile(
        "mma.sync.aligned.m16n8k16.row.col.f32.bf16.bf16.f32 "
        "{%0,%1,%2,%3}, {%4,%5,%6,%7}, {%8,%9}, {%0,%1,%2,%3};"
        : "+f"(d[0]), "+f"(d[1]), "+f"(d[2]), "+f"(d[3])
        : "r"(a[0]), "r"(a[1]), "r"(a[2]), "r"(a[3]), "r"(b[0]), "r"(b[1]));
}

// ---------------- weight pad+split ----------------
__global__ void k_wconv(const float* __restrict__ W, int Nout, int K, int NoutPad, int Kpad,
                        __nv_bfloat16* __restrict__ Ph, __nv_bfloat16* __restrict__ Pl) {
    int idx = blockIdx.x * blockDim.x + threadIdx.x;
    if (idx >= NoutPad * Kpad) return;
    int n = idx / Kpad, k = idx - n * Kpad;
    float w = (n < Nout && k < K) ? W[(size_t)n * K + k] : 0.0f;
    __nv_bfloat16 h, l;
    split_bf16(w, h, l);
    Ph[idx] = h;
    Pl[idx] = l;
}

// ---------------- prep (validated R1) ----------------
__global__ void k_prep(const float* __restrict__ y_t, const float* __restrict__ x_ens,
                       const float* __restrict__ xppm, const float* __restrict__ xpdm,
                       const float* __restrict__ y_prev, const float* __restrict__ F,
                       const float* __restrict__ Hm,
                       float* __restrict__ feat, float* __restrict__ innov) {
    __shared__ float sF[256], sH[128], sxbar[16][16], sxpm[16][16], sinn[16][8];
    int tid = threadIdx.x;
    if (tid < 256) sF[tid] = F[tid];
    if (tid < 128) sH[tid] = Hm[tid];
    int bl = tid >> 4, m = tid & 15;
    int b = blockIdx.x * 16 + bl;
    float s = 0.0f;
    #pragma unroll 4
    for (int si = 0; si < S_; si++) s += x_ens[((size_t)si * B_ + b) * M_ + m];
    sxbar[bl][m] = s * (1.0f / S_);
    __syncthreads();
    float xp = 0.0f;
    #pragma unroll
    for (int j = 0; j < 16; j++) xp += sF[m * 16 + j] * sxbar[bl][j];
    sxpm[bl][m] = xp;
    __syncthreads();
    if (m < 8) {
        float yp = 0.0f;
        #pragma unroll
        for (int j = 0; j < 16; j++) yp += sH[m * 16 + j] * sxpm[bl][j];
        float inn = y_t[b * N_ + m] - yp;
        sinn[bl][m] = inn;
        innov[b * N_ + m] = inn;
    }
    __syncthreads();
    for (int e = tid; e < 16 * IN_; e += 256) {
        int bb = e / IN_, c = e % IN_;
        int gb = blockIdx.x * 16 + bb;
        float v;
        if (c < 16)      v = sxbar[bb][c]      - xpdm[gb * M_ + c];
        else if (c < 24) v = sinn[bb][c - 16];
        else if (c < 40) v = sxbar[bb][c - 24] - xppm[gb * M_ + (c - 24)];
        else             v = y_t[gb * N_ + (c - 40)] - y_prev[gb * N_ + (c - 40)];
        feat[gb * IN_ + c] = v;
    }
}

// ---------------- feat*cdrop -> padded planes [ROWS][64] ----------------
__global__ void k_dropin(const float* __restrict__ feat, const float* __restrict__ u_in,
                         const float* __restrict__ p_ptr,
                         __nv_bfloat16* __restrict__ Oh, __nv_bfloat16* __restrict__ Ol) {
    int idx = blockIdx.x * blockDim.x + threadIdx.x;
    if (idx >= ROWS_ * 64) return;
    int r = idx >> 6, c = idx & 63;
    float v = 0.0f;
    if (c < IN_) {
        float plog = *p_ptr;
        int b = r & (B_ - 1);
        v = feat[b * IN_ + c] * cfac(u_in[(size_t)r * IN_ + c], plog, 1.0f + __expf(plog));
    }
    __nv_bfloat16 h, l;
    split_bf16(v, h, l);
    Oh[idx] = h;
    Ol[idx] = l;
}

// ---------------- h_ens -> padded planes [ROWS][256] ----------------
__global__ void k_hconv(const float* __restrict__ h_ens,
                        __nv_bfloat16* __restrict__ Oh, __nv_bfloat16* __restrict__ Ol) {
    size_t idx = (size_t)blockIdx.x * blockDim.x + threadIdx.x;
    if (idx >= (size_t)ROWS_ * 256) return;
    int r = (int)(idx >> 8), c = (int)(idx & 255);
    float v = (c < H_) ? h_ens[(size_t)r * H_ + c] : 0.0f;
    __nv_bfloat16 h, l;
    split_bf16(v, h, l);
    Oh[idx] = h;
    Ol[idx] = l;
}

// ---------------------------------------------------------------------------
// bf16-split HMMA GEMM. Tile 128x64, BK=16, 8 warps (warp tile 32x32),
// double-buffered cp.async, <=48KB smem.
// A planes [rows][Kpad], W planes [NoutPad][Kpad] (zero-padded).
// EPI: 0 = +bias -> fp32 out [rows][Nout] (guard cols)
//      1 = relu -> bf16 planes (stride Ostride, pads get zeros)
//      2 = relu * cdrop(u_out) -> bf16 planes
// ---------------------------------------------------------------------------
#define STG 18432
#define SMEM_DYN 37248
template <int EPI>
__global__ void __launch_bounds__(256) mma_gemm(
    const __nv_bfloat16* __restrict__ Ah, const __nv_bfloat16* __restrict__ Al, int Kpad,
    const __nv_bfloat16* __restrict__ Wh, const __nv_bfloat16* __restrict__ Wl,
    const float* __restrict__ bias, int Nout,
    float* __restrict__ outF,
    __nv_bfloat16* __restrict__ Oh, __nv_bfloat16* __restrict__ Ol, int Ostride,
    const float* __restrict__ u_outp, const float* __restrict__ p_outp) {
    extern __shared__ char smem[];
    const uint32_t su = smem_u32(smem);
    const int tid = threadIdx.x;
    const int lane = tid & 31;
    const int wm = (tid >> 5) & 3;   // warp row granule (32)
    const int wn = tid >> 7;         // warp col granule (32)
    const int row0 = blockIdx.x * 128;
    const int n0 = blockIdx.y * 64;
    const int NK = Kpad / 16;

    float* sBias = (float*)(smem + 2 * STG);
    if (tid < 64) sBias[tid] = (n0 + tid < Nout) ? bias[n0 + tid] : 0.0f;

    // cp.async indices: A planes 256 chunks (r=tid>>1, cg=tid&1); B 128 chunks
    const int ar = tid >> 1, acg = tid & 1;

    // issue stage loader as a lambda-free macro
    #define LOADSTAGE(sidx, kc) do { \
        uint32_t sb = su + (sidx) * STG; \
        int kk = (kc) * 16 + acg * 8; \
        cp16(sb + ar * 48 + acg * 16, Ah + (size_t)(row0 + ar) * Kpad + kk); \
        cp16(sb + 6144 + ar * 48 + acg * 16, Al + (size_t)(row0 + ar) * Kpad + kk); \
        if (tid < 128) { \
            cp16(sb + 12288 + ar * 48 + acg * 16, Wh + (size_t)(n0 + ar) * Kpad + kk); \
            cp16(sb + 15360 + ar * 48 + acg * 16, Wl + (size_t)(n0 + ar) * Kpad + kk); \
        } \
        CP_COMMIT(); \
    } while (0)

    float d[2][4][4];
    #pragma unroll
    for (int i = 0; i < 2; i++)
        #pragma unroll
        for (int j = 0; j < 4; j++)
            #pragma unroll
            for (int k = 0; k < 4; k++) d[i][j][k] = 0.0f;

    // per-thread ldmatrix base offsets
    const uint32_t a_off = ((wm * 32 + (lane & 15)) * 24 + (lane >> 4) * 8) * 2;
    const uint32_t b_off = ((wn * 32 + (lane & 7) + ((lane >> 4) << 3)) * 24 +
                            (((lane >> 3) & 1) << 3)) * 2;

    LOADSTAGE(0, 0);
    for (int kc = 0; kc < NK; kc++) {
        if (kc + 1 < NK) {
            LOADSTAGE((kc + 1) & 1, kc + 1);
            asm volatile("cp.async.wait_group 1;" ::: "memory");
        } else {
            asm volatile("cp.async.wait_group 0;" ::: "memory");
        }
        __syncthreads();
        uint32_t sb = su + (kc & 1) * STG;
        uint32_t ah[2][4], al[2][4], bh[4][2], bl[4][2], q[4];
        #pragma unroll
        for (int mt = 0; mt < 2; mt++) {
            ldm4(ah[mt], sb + a_off + mt * 768);
            ldm4(al[mt], sb + 6144 + a_off + mt * 768);
        }
        #pragma unroll
        for (int p = 0; p < 2; p++) {
            ldm4(q, sb + 12288 + b_off + p * 768);
            bh[p * 2][0] = q[0]; bh[p * 2][1] = q[1];
            bh[p * 2 + 1][0] = q[2]; bh[p * 2 + 1][1] = q[3];
            ldm4(q, sb + 15360 + b_off + p * 768);
            bl[p * 2][0] = q[0]; bl[p * 2][1] = q[1];
            bl[p * 2 + 1][0] = q[2]; bl[p * 2 + 1][1] = q[3];
        }
        #pragma unroll
        for (int mt = 0; mt < 2; mt++)
            #pragma unroll
            for (int nt = 0; nt < 4; nt++) {
                mma16816(d[mt][nt], ah[mt], bh[nt]);
                mma16816(d[mt][nt], ah[mt], bl[nt]);
                mma16816(d[mt][nt], al[mt], bh[nt]);
            }
        __syncthreads();
    }

    // ---- stage accums to smem [128][65] fp32 ----
    float* stage = (float*)smem;
    {
        int lr = lane >> 2, lc = (lane & 3) * 2;
        #pragma unroll
        for (int mt = 0; mt < 2; mt++)
            #pragma unroll
            for (int nt = 0; nt < 4; nt++) {
                int rr = wm * 32 + mt * 16 + lr;
                int cc = wn * 32 + nt * 8 + lc;
                stage[rr * 65 + cc] = d[mt][nt][0];
                stage[rr * 65 + cc + 1] = d[mt][nt][1];
                stage[(rr + 8) * 65 + cc] = d[mt][nt][2];
                stage[(rr + 8) * 65 + cc + 1] = d[mt][nt][3];
            }
    }
    __syncthreads();

    if (EPI == 0) {
        for (int i = tid; i < 128 * 64; i += 256) {
            int r = i >> 6, c = i & 63;
            if (n0 + c < Nout)
                outF[(size_t)(row0 + r) * Nout + n0 + c] = stage[r * 65 + c] + sBias[c];
        }
    } else {
        float pout = 0.0f, fout = 0.0f;
        if (EPI == 2) { pout = *p_outp; fout = 1.0f + __expf(pout); }
        for (int i = tid; i < 128 * 32; i += 256) {
            int r = i >> 5, c = (i & 31) * 2;
            float v0 = fmaxf(stage[r * 65 + c] + sBias[c], 0.0f);
            float v1 = fmaxf(stage[r * 65 + c + 1] + sBias[c + 1], 0.0f);
            if (EPI == 2) {
                float2 uu = *(const float2*)(u_outp + (size_t)(row0 + r) * Ostride + n0 + c);
                v0 *= cfac(uu.x, pout, fout);
                v1 *= cfac(uu.y, pout, fout);
            }
            __nv_bfloat16 h0, l0, h1, l1;
            split_bf16(v0, h0, l0);
            split_bf16(v1, h1, l1);
            __nv_bfloat162 ph, pl;
            ph.x = h0; ph.y = h1; pl.x = l0; pl.y = l1;
            *(__nv_bfloat162*)(Oh + (size_t)(row0 + r) * Ostride + n0 + c) = ph;
            *(__nv_bfloat162*)(Ol + (size_t)(row0 + r) * Ostride + n0 + c) = pl;
        }
    }
    #undef LOADSTAGE
}

// ---------------- GRU -> dropped-h padded planes [ROWS][256] ----------------
__global__ void k_gru(const float* __restrict__ gi, const float* __restrict__ gh,
                      const float* __restrict__ h_ens, const float* __restrict__ u_fc1,
                      const float* __restrict__ p_ptr,
                      __nv_bfloat16* __restrict__ Oh, __nv_bfloat16* __restrict__ Ol) {
    size_t idx = (size_t)blockIdx.x * blockDim.x + threadIdx.x;
    if (idx >= (size_t)ROWS_ * 256) return;
    int r = (int)(idx >> 8), j = (int)(idx & 255);
    float v = 0.0f;
    if (j < H_) {
        size_t gb = (size_t)r * 720;
        float ir = gi[gb + j], iz = gi[gb + 240 + j], in_ = gi[gb + 480 + j];
        float hr = gh[gb + j], hz = gh[gb + 240 + j], hn = gh[gb + 480 + j];
        float rg = sigm(ir + hr);
        float z = sigm(iz + hz);
        float ng = tanhf(in_ + rg * hn);
        float h = h_ens[(size_t)r * H_ + j];
        float hnew = (1.0f - z) * ng + z * h;
        float plog = *p_ptr;
        v = hnew * cfac(u_fc1[(size_t)r * H_ + j], plog, 1.0f + __expf(plog));
    }
    __nv_bfloat16 h, l;
    split_bf16(v, h, l);
    Oh[idx] = h;
    Ol[idx] = l;
}

// ---------------- Kalman: out = F@x_ens + K@innov ----------------
__global__ void k_kalman(const float* __restrict__ Kv, const float* __restrict__ x_ens,
                         const float* __restrict__ F, const float* __restrict__ innov,
                         float* __restrict__ out) {
    __shared__ float sF[256];
    int tid = threadIdx.x;
    if (tid < 256) sF[tid] = F[tid];
    __syncthreads();
    int row = blockIdx.x * 16 + (tid >> 4);
    int m = tid & 15;
    int b = row & (B_ - 1);
    const float* xr = x_ens + (size_t)row * M_;
    float acc = 0.0f;
    #pragma unroll
    for (int j = 0; j < 16; j++) acc += sF[m * 16 + j] * xr[j];
    const float* kr = Kv + (size_t)row * 128 + m * 8;
    const float* ir = innov + b * 8;
    #pragma unroll
    for (int n = 0; n < 8; n++) acc += kr[n] * ir[n];
    out[(size_t)row * M_ + m] = acc;
}

// ---------------- regularizer ----------------
__global__ void k_reg_sums(const float* __restrict__ W_in, const float* __restrict__ W_fc1,
                           const float* __restrict__ W_fc2, double* __restrict__ reg) {
    __shared__ double sd[256];
    int l = blockIdx.x;
    const float* W = (l == 0) ? W_in : (l == 1) ? W_fc1 : W_fc2;
    int n = (l == 0) ? H_ * IN_ : (l == 1) ? O1_ * H_ : M_ * N_ * O1_;
    double s = 0.0;
    for (int i = threadIdx.x; i < n; i += 256) { float w = W[i]; s += (double)w * (double)w; }
    sd[threadIdx.x] = s;
    __syncthreads();
    for (int o = 128; o > 0; o >>= 1) {
        if (threadIdx.x < o) sd[threadIdx.x] += sd[threadIdx.x + o];
        __syncthreads();
    }
    if (threadIdx.x == 0) reg[l] = sd[0];
}
__global__ void k_reg_final(const double* __restrict__ reg, const float* __restrict__ p_in,
                            const float* __restrict__ p_fc1, const float* __restrict__ p_fc2,
                            float* __restrict__ out_reg) {
    double tot = 0.0;
    float pl[3] = {*p_in, *p_fc1, *p_fc2};
    double fan[3] = {(double)IN_, (double)H_, (double)O1_};
    #pragma unroll
    for (int l = 0; l < 3; l++) {
        double p = 1.0 / (1.0 + exp(-(double)pl[l]));
        tot += reg[l] / (1.0 - p) + fan[l] * (p * log(p) + (1.0 - p) * log1p(-p));
    }
    if (threadIdx.x < S_) out_reg[threadIdx.x] = (float)tot;
}

// ---------------- launch ----------------
extern "C" void kernel_launch(void* const* d_in, const int* in_sizes, int n_in,
                              void* d_out, int out_size) {
    const float* y_t    = (const float*)d_in[0];
    const float* x_ens  = (const float*)d_in[1];
    const float* xppm   = (const float*)d_in[2];
    const float* xpdm   = (const float*)d_in[3];
    const float* y_prev = (const float*)d_in[4];
    const float* h_ens  = (const float*)d_in[5];
    const float* F      = (const float*)d_in[6];
    const float* Hm     = (const float*)d_in[7];
    const float* W_in   = (const float*)d_in[8];
    const float* b_in   = (const float*)d_in[9];
    const float* W_ih   = (const float*)d_in[10];
    const float* b_ih   = (const float*)d_in[11];
    const float* W_hh   = (const float*)d_in[12];
    const float* b_hh   = (const float*)d_in[13];
    const float* W_fc1  = (const float*)d_in[14];
    const float* b_fc1  = (const float*)d_in[15];
    const float* W_fc2  = (const float*)d_in[16];
    const float* b_fc2  = (const float*)d_in[17];
    const float* p_in   = (const float*)d_in[18];
    const float* p_fc1  = (const float*)d_in[19];
    const float* p_fc2  = (const float*)d_in[20];
    const float* u_in   = (const float*)d_in[21];
    const float* u_fc1  = (const float*)d_in[22];
    const float* u_fc2  = (const float*)d_in[23];
    float* out = (float*)d_out;

    float *gip, *ghp, *kvp, *featp, *innp;
    double* regp;
    __nv_bfloat16 *fh, *fl, *x1h, *x1l, *hh, *hl, *hdh, *hdl, *x2h, *x2l;
    __nv_bfloat16 *wih, *wil, *wihh, *wihl, *whhh, *whhl, *wf1h, *wf1l, *wf2h, *wf2l;
    cudaGetSymbolAddress((void**)&gip, g_gi);
    cudaGetSymbolAddress((void**)&ghp, g_gh);
    cudaGetSymbolAddress((void**)&kvp, g_kv);
    cudaGetSymbolAddress((void**)&featp, g_feat);
    cudaGetSymbolAddress((void**)&innp, g_innov);
    cudaGetSymbolAddress((void**)&regp, g_reg);
    cudaGetSymbolAddress((void**)&fh, g_fh);
    cudaGetSymbolAddress((void**)&fl, g_fl);
    cudaGetSymbolAddress((void**)&x1h, g_x1h);
    cudaGetSymbolAddress((void**)&x1l, g_x1l);
    cudaGetSymbolAddress((void**)&hh, g_hh);
    cudaGetSymbolAddress((void**)&hl, g_hl);
    cudaGetSymbolAddress((void**)&hdh, g_hdh);
    cudaGetSymbolAddress((void**)&hdl, g_hdl);
    cudaGetSymbolAddress((void**)&x2h, g_x2h);
    cudaGetSymbolAddress((void**)&x2l, g_x2l);
    cudaGetSymbolAddress((void**)&wih, g_wi_h);
    cudaGetSymbolAddress((void**)&wil, g_wi_l);
    cudaGetSymbolAddress((void**)&wihh, g_wih_h);
    cudaGetSymbolAddress((void**)&wihl, g_wih_l);
    cudaGetSymbolAddress((void**)&whhh, g_whh_h);
    cudaGetSymbolAddress((void**)&whhl, g_whh_l);
    cudaGetSymbolAddress((void**)&wf1h, g_wf1_h);
    cudaGetSymbolAddress((void**)&wf1l, g_wf1_l);
    cudaGetSymbolAddress((void**)&wf2h, g_wf2_h);
    cudaGetSymbolAddress((void**)&wf2l, g_wf2_l);

    k_wconv<<<(256 * 64 + 255) / 256, 256>>>(W_in, 240, 48, 256, 64, wih, wil);
    k_wconv<<<(768 * 256 + 255) / 256, 256>>>(W_ih, 720, 240, 768, 256, wihh, wihl);
    k_wconv<<<(768 * 256 + 255) / 256, 256>>>(W_hh, 720, 240, 768, 256, whhh, whhl);
    k_wconv<<<(512 * 256 + 255) / 256, 256>>>(W_fc1, 512, 240, 512, 256, wf1h, wf1l);
    k_wconv<<<(128 * 512 + 255) / 256, 256>>>(W_fc2, 128, 512, 128, 512, wf2h, wf2l);

    k_prep<<<B_ / 16, 256>>>(y_t, x_ens, xppm, xpdm, y_prev, F, Hm, featp, innp);
    k_reg_sums<<<3, 256>>>(W_in, W_fc1, W_fc2, regp);
    k_dropin<<<(ROWS_ * 64 + 255) / 256, 256>>>(featp, u_in, p_in, fh, fl);
    k_hconv<<<(int)(((size_t)ROWS_ * 256 + 255) / 256), 256>>>(h_ens, hh, hl);

    // g1: x1 = relu(dropped_feat @ W_in^T + b_in) -> planes[ROWS][256]
    mma_gemm<1><<<dim3(ROWS_ / 128, 4), 256, SMEM_DYN>>>(
        fh, fl, 64, wih, wil, b_in, 240, nullptr, x1h, x1l, 256, nullptr, nullptr);
    // g2: gi = x1 @ W_ih^T + b_ih  (fp32 [ROWS][720])
    mma_gemm<0><<<dim3(ROWS_ / 128, 12), 256, SMEM_DYN>>>(
        x1h, x1l, 256, wihh, wihl, b_ih, 720, gip, nullptr, nullptr, 0, nullptr, nullptr);
    // g3: gh = h_ens @ W_hh^T + b_hh
    mma_gemm<0><<<dim3(ROWS_ / 128, 12), 256, SMEM_DYN>>>(
        hh, hl, 256, whhh, whhl, b_hh, 720, ghp, nullptr, nullptr, 0, nullptr, nullptr);
    // GRU -> dropped-h planes
    k_gru<<<(int)(((size_t)ROWS_ * 256 + 255) / 256), 256>>>(gip, ghp, h_ens, u_fc1, p_fc1, hdh, hdl);
    // g4: x2 = cdrop(relu(hd @ W_fc1^T + b_fc1), u_fc2) -> planes[ROWS][512]
    mma_gemm<2><<<dim3(ROWS_ / 128, 8), 256, SMEM_DYN>>>(
        hdh, hdl, 256, wf1h, wf1l, b_fc1, 512, nullptr, x2h, x2l, 512, u_fc2, p_fc2);
    // g5: Kv = x2 @ W_fc2^T + b_fc2  (fp32 [ROWS][128])
    mma_gemm<0><<<dim3(ROWS_ / 128, 2), 256, SMEM_DYN>>>(
        x2h, x2l, 512, wf2h, wf2l, b_fc2, 128, kvp, nullptr, nullptr, 0, nullptr, nullptr);
    // Kalman update
    k_kalman<<<ROWS_ / 16, 256>>>(kvp, x_ens, F, innp, out);

    k_reg_final<<<1, 32>>>(regp, p_in, p_fc1, p_fc2, out + (size_t)ROWS_ * M_);
}